// round 14
// baseline (speedup 1.0000x reference)
#include <cuda_runtime.h>
#include <math.h>
#include <cstdint>

#define BATCH 64
#define SEQ   512
#define EDIM  256
#define HDIM2 256
#define G4H   1024
#define NTAGS 9
#define NTOK  (BATCH*SEQ)
#define Y0    112           // position blocks precomputed by launch 1
#define NWORK 20            // persistent GEMM workers in the fused kernel

typedef unsigned long long u64;

// xg layout: [dir][pos][batch][1024]
__device__ float g_xg[2u*NTOK*G4H];
__device__ float g_h [2u*NTOK*HDIM2];
__device__ float g_feats[NTOK*NTAGS];
__device__ float g_llh[BATCH];
__device__ int   g_cnt[16];      // per-(dir,bg8) LSTM step counters
__device__ int   g_xgcnt[512];   // per-(dir, posblock y) GEMM completion counters

__device__ __forceinline__ void fma2(u64& acc, u64 a, u64 b) {
    asm("fma.rn.f32x2 %0, %1, %2, %0;" : "+l"(acc) : "l"(a), "l"(b));
}
__device__ __forceinline__ u64 pack2(float x, float y) {
    u64 r; asm("mov.b64 %0, {%1, %2};" : "=l"(r) : "f"(x), "f"(y)); return r;
}
__device__ __forceinline__ float foldlohi(u64 v) {
    float lo, hi; asm("mov.b64 {%0, %1}, %2;" : "=f"(lo), "=f"(hi) : "l"(v)); return lo + hi;
}
__device__ __forceinline__ float2 unpk(u64 v) {
    float2 r; asm("mov.b64 {%0, %1}, %2;" : "=f"(r.x), "=f"(r.y) : "l"(v)); return r;
}
__device__ __forceinline__ float sigf(float x) { return __fdividef(1.f, 1.f + __expf(-x)); }
__device__ __forceinline__ float tanhfast(float x) {
    return 2.f * __fdividef(1.f, 1.f + __expf(-2.f * x)) - 1.f;
}

// ============================================================================
// GEMM tile body (consumption-ordered): tile (ntile, y) covers positions
// {pos0, pos0+1} (pos0 = 2y fwd / 510-2y bwd) x 64 batches x 128 gate cols.
// Tile row r: pos = pos0 + (r>>6), b = r&63. Shared by launch-1 kernel and
// the fused kernel's worker path.
// ============================================================================
__device__ __forceinline__ void gemm_tile(
    float* As, float* Bs, int ntile, int y, int tid,
    const int* __restrict__ sent, const float* __restrict__ emb,
    const float* __restrict__ wihf, const float* __restrict__ wihb,
    const float* __restrict__ bihf, const float* __restrict__ bhhf,
    const float* __restrict__ bihb, const float* __restrict__ bhhb)
{
    const int dir  = ntile >> 3;
    const int pos0 = dir ? (510 - 2 * y) : (2 * y);
    const float* __restrict__ W = dir ? wihb : wihf;

    const int rowA = tid >> 2;               // batch 0..63
    const int f4k  = tid & 3;
    const int idx0 = sent[rowA * SEQ + pos0];
    const int idx1 = sent[rowA * SEQ + pos0 + 1];
    const int nlb0 = (ntile * 128 + rowA) & 1023;
    const int nlb1 = (ntile * 128 + rowA + 64) & 1023;

    float4 av0 = *reinterpret_cast<const float4*>(emb + (size_t)idx0 * EDIM + f4k * 4);
    float4 av1 = *reinterpret_cast<const float4*>(emb + (size_t)idx1 * EDIM + f4k * 4);
    float4 bv0 = *reinterpret_cast<const float4*>(W + (size_t)nlb0 * EDIM + f4k * 4);
    float4 bv1 = *reinterpret_cast<const float4*>(W + (size_t)nlb1 * EDIM + f4k * 4);

    u64 acc[4][8];
#pragma unroll
    for (int i = 0; i < 4; i++)
#pragma unroll
        for (int j = 0; j < 8; j++) acc[i][j] = 0ull;

    const int ty = tid >> 4, tx = tid & 15;

    for (int kb = 0; kb < EDIM; kb += 16) {
        As[(f4k * 4 + 0) * 132 + rowA] = av0.x;
        As[(f4k * 4 + 1) * 132 + rowA] = av0.y;
        As[(f4k * 4 + 2) * 132 + rowA] = av0.z;
        As[(f4k * 4 + 3) * 132 + rowA] = av0.w;
        As[(f4k * 4 + 0) * 132 + rowA + 64] = av1.x;
        As[(f4k * 4 + 1) * 132 + rowA + 64] = av1.y;
        As[(f4k * 4 + 2) * 132 + rowA + 64] = av1.z;
        As[(f4k * 4 + 3) * 132 + rowA + 64] = av1.w;
        Bs[(f4k * 4 + 0) * 128 + rowA] = bv0.x;
        Bs[(f4k * 4 + 1) * 128 + rowA] = bv0.y;
        Bs[(f4k * 4 + 2) * 128 + rowA] = bv0.z;
        Bs[(f4k * 4 + 3) * 128 + rowA] = bv0.w;
        Bs[(f4k * 4 + 0) * 128 + rowA + 64] = bv1.x;
        Bs[(f4k * 4 + 1) * 128 + rowA + 64] = bv1.y;
        Bs[(f4k * 4 + 2) * 128 + rowA + 64] = bv1.z;
        Bs[(f4k * 4 + 3) * 128 + rowA + 64] = bv1.w;
        __syncthreads();

        if (kb + 16 < EDIM) {
            av0 = *reinterpret_cast<const float4*>(emb + (size_t)idx0 * EDIM + kb + 16 + f4k * 4);
            av1 = *reinterpret_cast<const float4*>(emb + (size_t)idx1 * EDIM + kb + 16 + f4k * 4);
            bv0 = *reinterpret_cast<const float4*>(W + (size_t)nlb0 * EDIM + kb + 16 + f4k * 4);
            bv1 = *reinterpret_cast<const float4*>(W + (size_t)nlb1 * EDIM + kb + 16 + f4k * 4);
        }

#pragma unroll
        for (int k = 0; k < 16; k++) {
            const float* ap = As + k * 132 + ty * 8;
            ulonglong2 A01 = *reinterpret_cast<const ulonglong2*>(ap);
            ulonglong2 A23 = *reinterpret_cast<const ulonglong2*>(ap + 4);
            const float* bp = Bs + k * 128 + tx * 8;
            float4 b0 = *reinterpret_cast<const float4*>(bp);
            float4 b1 = *reinterpret_cast<const float4*>(bp + 4);
            u64 am[4] = {A01.x, A01.y, A23.x, A23.y};
            u64 bn[8];
            bn[0] = pack2(b0.x, b0.x); bn[1] = pack2(b0.y, b0.y);
            bn[2] = pack2(b0.z, b0.z); bn[3] = pack2(b0.w, b0.w);
            bn[4] = pack2(b1.x, b1.x); bn[5] = pack2(b1.y, b1.y);
            bn[6] = pack2(b1.z, b1.z); bn[7] = pack2(b1.w, b1.w);
#pragma unroll
            for (int i = 0; i < 4; i++)
#pragma unroll
                for (int j = 0; j < 8; j++) fma2(acc[i][j], am[i], bn[j]);
        }
        __syncthreads();
    }

    const int nl0 = (ntile * 128 + tx * 8) & 1023;
    const float* __restrict__ bih = dir ? bihb : bihf;
    const float* __restrict__ bhh = dir ? bhhb : bhhf;
    float bias[8];
#pragma unroll
    for (int j = 0; j < 8; j++) bias[j] = bih[nl0 + j] + bhh[nl0 + j];

#pragma unroll
    for (int i2 = 0; i2 < 4; i2++) {
        float2 v[8];
#pragma unroll
        for (int j = 0; j < 8; j++) v[j] = unpk(acc[i2][j]);
        const int m0 = ty * 8 + 2 * i2;            // local rows m0, m0+1
        const int posr = pos0 + (m0 >> 6);
        const int br   = m0 & 63;
        float4 oa0, oa1, ob0, ob1;
        oa0.x = v[0].x + bias[0]; oa0.y = v[1].x + bias[1]; oa0.z = v[2].x + bias[2]; oa0.w = v[3].x + bias[3];
        oa1.x = v[4].x + bias[4]; oa1.y = v[5].x + bias[5]; oa1.z = v[6].x + bias[6]; oa1.w = v[7].x + bias[7];
        ob0.x = v[0].y + bias[0]; ob0.y = v[1].y + bias[1]; ob0.z = v[2].y + bias[2]; ob0.w = v[3].y + bias[3];
        ob1.x = v[4].y + bias[4]; ob1.y = v[5].y + bias[5]; ob1.z = v[6].y + bias[6]; ob1.w = v[7].y + bias[7];
        float* p0 = g_xg + ((size_t)((dir * SEQ + posr) * BATCH + br)) * G4H + nl0;
        float* p1 = g_xg + ((size_t)((dir * SEQ + posr) * BATCH + br + 1)) * G4H + nl0;
        *reinterpret_cast<float4*>(p0)     = oa0;
        *reinterpret_cast<float4*>(p0 + 4) = oa1;
        *reinterpret_cast<float4*>(p1)     = ob0;
        *reinterpret_cast<float4*>(p1 + 4) = ob1;
    }
}

// ============================================================================
// Launch 1: full-width GEMM for y in [0, Y0). Block (0,0) resets all flags.
// ============================================================================
__global__ __launch_bounds__(256) void gemm_head_kernel(
    const int* __restrict__ sent, const float* __restrict__ emb,
    const float* __restrict__ wihf, const float* __restrict__ wihb,
    const float* __restrict__ bihf, const float* __restrict__ bhhf,
    const float* __restrict__ bihb, const float* __restrict__ bhhb)
{
    __shared__ float As[16 * 132];
    __shared__ float Bs[16 * 128];
    const int tid = threadIdx.x;
    if (blockIdx.x == 0 && blockIdx.y == 0) {
        g_xgcnt[tid] = 0;
        g_xgcnt[tid + 256] = 0;
        if (tid < 16) g_cnt[tid] = 0;
    }
    gemm_tile(As, Bs, blockIdx.x, blockIdx.y, tid,
              sent, emb, wihf, wihb, bihf, bhhf, bihb, bhhb);
}

// ============================================================================
// Launch 2 (fused): blocks 0..127 = R9-champion LSTM; blocks 128..147 = 20
// persistent GEMM workers producing y in [Y0, 256) in consumption order.
// All 148 CTAs co-resident (1/SM) -> deadlock-free.
// ============================================================================
#define HLD    260
#define PRE_LD 65
#define FUSED_SMEM ((8*HLD + 128*PRE_LD) * 4)   // 41600 B (>= GEMM's 16640)

__global__ __launch_bounds__(256, 1) void fused_kernel(
    const float* __restrict__ whhf, const float* __restrict__ whhb,
    const int* __restrict__ sent, const float* __restrict__ emb,
    const float* __restrict__ wihf, const float* __restrict__ wihb,
    const float* __restrict__ bihf, const float* __restrict__ bhhf,
    const float* __restrict__ bihb, const float* __restrict__ bhhb)
{
    extern __shared__ float sm[];
    const int tid = threadIdx.x;

    if (blockIdx.x >= 128) {
        // ---------------- GEMM worker path ----------------
        float* As = sm;                 // 16*132
        float* Bs = sm + 16 * 132;      // 16*128
        const int w = blockIdx.x - 128;
        const int ntiles_total = (256 - Y0) * 16;
        for (int tau = w; tau < ntiles_total; tau += NWORK) {
            const int y = Y0 + (tau >> 4);
            const int ntile = tau & 15;
            gemm_tile(As, Bs, ntile, y, tid,
                      sent, emb, wihf, wihb, bihf, bhhf, bihb, bhhb);
            __threadfence();
            __syncthreads();
            if (tid == 0) atomicAdd(&g_xgcnt[(ntile >> 3) * 256 + y], 1);
            __syncthreads();
        }
        return;
    }

    // ---------------- LSTM path (R9 champion body) ----------------
    float* hs  = sm;                    // [8][HLD] staged h_prev
    float* pre = sm + 8 * HLD;          // [128][PRE_LD]

    const int blk = blockIdx.x;
    const int dir = blk >> 6;
    const int bg  = (blk >> 3) & 7;
    const int ug  = blk & 7;
    const float* __restrict__ whh = dir ? whhb : whhf;

    const int kc = tid & 7;           // k slice
    const int r4 = tid >> 3;          // local unit 0..31 -> rows G*256 + ug*32 + r4

    // register weights: 4 gate rows x 32 k (16 pairs) each
    u64 w[4][16];
#pragma unroll
    for (int G = 0; G < 4; G++) {
        const float* wr = whh + (size_t)(G * 256 + ug * 32 + r4) * HDIM2;
#pragma unroll
        for (int q = 0; q < 8; q++) {
            ulonglong2 v = *reinterpret_cast<const ulonglong2*>(wr + q * 32 + kc * 4);
            w[G][2 * q] = v.x; w[G][2 * q + 1] = v.y;
        }
    }

    const int gb = tid >> 5;          // gate phase: batch 0..7
    const int gu = tid & 31;          // unit-in-slice 0..31
    const int b_glob = bg * 8 + gb;
    const int unit = ug * 32 + gu;
    const int cnt_idx = dir * 8 + bg;
    float c_state = 0.f;

    for (int t = 0; t < SEQ; t++) {
        const int pos = dir ? (SEQ - 1 - t) : t;

        // wait for workers to finish this position block (y changes every 2 steps)
        if ((t & 1) == 0 && (t >> 1) >= Y0) {
            if (tid == 0) {
                volatile int* xc = &g_xgcnt[dir * 256 + (t >> 1)];
                while (*xc < 8) { }
            }
            __syncthreads();
        }

        // prefetch x-preacts before the inter-CTA wait
        const float* xp = g_xg + ((size_t)((dir * SEQ + pos) * BATCH + b_glob)) * G4H + unit;
        float x0 = __ldcs(xp);
        float x1 = __ldcs(xp + 256);
        float x2 = __ldcs(xp + 512);
        float x3 = __ldcs(xp + 768);

        if (t > 0) {
            if (tid == 0) {
                volatile int* c = &g_cnt[cnt_idx];
                const int target = 8 * t;
                while (*c < target) { }
            }
            __syncthreads();
            const int ppos = dir ? (pos + 1) : (pos - 1);
#pragma unroll
            for (int q = 0; q < 2; q++) {
                const int id = tid + q * 256;
                const int b = id >> 6, kf4 = id & 63;
                float4 v = __ldcg(reinterpret_cast<const float4*>(
                    g_h + ((size_t)(dir * BATCH + bg * 8 + b) * SEQ + ppos) * HDIM2 + kf4 * 4));
                *reinterpret_cast<float4*>(hs + b * HLD + kf4 * 4) = v;
            }
            __syncthreads();

            // matvec: 4 gate rows x 8 batches x 32 k, 2 passes of 4 batches
#pragma unroll
            for (int p = 0; p < 2; p++) {
                u64 acc[4][4];
#pragma unroll
                for (int G = 0; G < 4; G++)
#pragma unroll
                    for (int b = 0; b < 4; b++) acc[G][b] = 0ull;
#pragma unroll
                for (int q = 0; q < 8; q++) {
#pragma unroll
                    for (int b = 0; b < 4; b++) {
                        const ulonglong2 hv = *reinterpret_cast<const ulonglong2*>(
                            hs + (p * 4 + b) * HLD + q * 32 + kc * 4);
#pragma unroll
                        for (int G = 0; G < 4; G++) {
                            fma2(acc[G][b], w[G][2 * q],     hv.x);
                            fma2(acc[G][b], w[G][2 * q + 1], hv.y);
                        }
                    }
                }
#pragma unroll
                for (int G = 0; G < 4; G++)
#pragma unroll
                    for (int b = 0; b < 4; b++)
                        pre[(G * 32 + r4) * PRE_LD + kc * 8 + p * 4 + b] = foldlohi(acc[G][b]);
            }
            __syncthreads();
        }

        // gate phase: thread owns (batch gb, unit gu)
        {
            float pi = x0, pf = x1, pg = x2, po = x3;
            if (t > 0) {
#pragma unroll
                for (int k8 = 0; k8 < 8; k8++) {
                    pi += pre[(0 * 32 + gu) * PRE_LD + k8 * 8 + gb];
                    pf += pre[(1 * 32 + gu) * PRE_LD + k8 * 8 + gb];
                    pg += pre[(2 * 32 + gu) * PRE_LD + k8 * 8 + gb];
                    po += pre[(3 * 32 + gu) * PRE_LD + k8 * 8 + gb];
                }
            }
            c_state = sigf(pf) * c_state + sigf(pi) * tanhfast(pg);
            const float hv = sigf(po) * tanhfast(c_state);
            __stcg(&g_h[((size_t)(dir * BATCH + b_glob) * SEQ + pos) * HDIM2 + unit], hv);
        }

        __syncthreads();
        if (tid == 0) {
            __threadfence();
            atomicAdd(&g_cnt[cnt_idx], 1);   // result unused -> RED
        }
    }
}

// ============================================================================
// Output projection
// ============================================================================
__global__ __launch_bounds__(256) void feats_kernel(
    const float* __restrict__ wout, const float* __restrict__ bout)
{
    __shared__ float wsm[NTAGS * 512];
    const int tid = threadIdx.x;
    for (int i = tid; i < NTAGS * 512; i += 256) wsm[i] = wout[i];
    __syncthreads();

    const int lane = tid & 31;
    const int warp = tid >> 5;

#pragma unroll
    for (int pass = 0; pass < 4; pass++) {
        const int m = blockIdx.x * 32 + pass * 8 + warp;
        const float* h0 = g_h + (size_t)m * HDIM2;
        const float* h1 = g_h + (size_t)NTOK * HDIM2 + (size_t)m * HDIM2;
        float acc[NTAGS];
#pragma unroll
        for (int tg = 0; tg < NTAGS; tg++) acc[tg] = 0.f;

#pragma unroll
        for (int kk = 0; kk < 16; kk++) {
            const int k = kk * 32 + lane;
            const float hv = (k < 256) ? h0[k] : h1[k - 256];
#pragma unroll
            for (int tg = 0; tg < NTAGS; tg++) acc[tg] += hv * wsm[tg * 512 + k];
        }
#pragma unroll
        for (int tg = 0; tg < NTAGS; tg++)
            for (int off = 16; off; off >>= 1)
                acc[tg] += __shfl_down_sync(0xffffffffu, acc[tg], off);
        if (lane == 0) {
#pragma unroll
            for (int tg = 0; tg < NTAGS; tg++)
                g_feats[(size_t)m * NTAGS + tg] = acc[tg] + bout[tg];
        }
    }
}

// ============================================================================
// CRF per-sequence llh (mask all-ones)
// ============================================================================
__global__ __launch_bounds__(32) void crf_kernel(
    const int* __restrict__ tags,
    const float* __restrict__ startt, const float* __restrict__ endt,
    const float* __restrict__ trans)
{
    const int b = blockIdx.x;
    const int lane = threadIdx.x;
    const float* __restrict__ em = g_feats + (size_t)b * SEQ * NTAGS;
    const int* __restrict__ tg = tags + (size_t)b * SEQ;

    float sc = 0.f;
    for (int s = lane; s < SEQ; s += 32) {
        const int tc = tg[s];
        sc += em[s * NTAGS + tc];
        if (s > 0) sc += trans[tg[s - 1] * NTAGS + tc];
    }
    for (int off = 16; off; off >>= 1) sc += __shfl_down_sync(0xffffffffu, sc, off);

    const int j = lane < NTAGS ? lane : NTAGS - 1;
    float tcol[NTAGS];
#pragma unroll
    for (int i = 0; i < NTAGS; i++) tcol[i] = trans[i * NTAGS + j];

    float alpha = startt[j] + em[j];
    for (int s = 1; s < SEQ; s++) {
        float v[NTAGS];
        float mx = -1e30f;
#pragma unroll
        for (int i = 0; i < NTAGS; i++) {
            const float ai = __shfl_sync(0xffffffffu, alpha, i);
            v[i] = ai + tcol[i];
            mx = fmaxf(mx, v[i]);
        }
        float sum = 0.f;
#pragma unroll
        for (int i = 0; i < NTAGS; i++) sum += __expf(v[i] - mx);
        alpha = mx + __logf(sum) + em[s * NTAGS + j];
    }

    float z = (lane < NTAGS) ? (alpha + endt[j]) : -1e30f;
    float mz = z;
    for (int off = 16; off; off >>= 1) mz = fmaxf(mz, __shfl_down_sync(0xffffffffu, mz, off));
    mz = __shfl_sync(0xffffffffu, mz, 0);
    float ez = __expf(z - mz);
    for (int off = 16; off; off >>= 1) ez += __shfl_down_sync(0xffffffffu, ez, off);

    if (lane == 0) {
        const float logZ = mz + __logf(ez);
        const float score = sc + startt[tg[0]] + endt[tg[SEQ - 1]];
        g_llh[b] = score - logZ;
    }
}

__global__ void final_kernel(float* out) {
    __shared__ float red[64];
    const int t = threadIdx.x;
    red[t] = g_llh[t];
    __syncthreads();
    for (int off = 32; off; off >>= 1) {
        if (t < off) red[t] += red[t + off];
        __syncthreads();
    }
    if (t == 0) out[0] = -red[0] / (float)BATCH;
}

// ============================================================================
extern "C" void kernel_launch(void* const* d_in, const int* in_sizes, int n_in,
                              void* d_out, int out_size)
{
    const int*   sent  = (const int*)  d_in[0];
    const int*   tags  = (const int*)  d_in[1];
    const float* emb   = (const float*)d_in[3];
    const float* wihf  = (const float*)d_in[4];
    const float* whhf  = (const float*)d_in[5];
    const float* bihf  = (const float*)d_in[6];
    const float* bhhf  = (const float*)d_in[7];
    const float* wihb  = (const float*)d_in[8];
    const float* whhb  = (const float*)d_in[9];
    const float* bihb  = (const float*)d_in[10];
    const float* bhhb  = (const float*)d_in[11];
    const float* wout  = (const float*)d_in[12];
    const float* bout  = (const float*)d_in[13];
    const float* startt= (const float*)d_in[14];
    const float* endt  = (const float*)d_in[15];
    const float* trans = (const float*)d_in[16];

    gemm_head_kernel<<<dim3(16, Y0), 256>>>(sent, emb, wihf, wihb, bihf, bhhf, bihb, bhhb);
    fused_kernel<<<148, 256, FUSED_SMEM>>>(whhf, whhb, sent, emb,
                                           wihf, wihb, bihf, bhhf, bihb, bhhb);
    feats_kernel<<<1024, 256>>>(wout, bout);
    crf_kernel<<<64, 32>>>(tags, startt, endt, trans);
    final_kernel<<<1, 64>>>((float*)d_out);
}

// round 16
// speedup vs baseline: 2.0424x; 2.0424x over previous
#include <cuda_runtime.h>
#include <cuda_bf16.h>
#include <math.h>
#include <cstdint>

#define BATCH 64
#define SEQ   512
#define EDIM  256
#define HDIM2 256
#define G4H   1024
#define NTAGS 9
#define NTOK  (BATCH*SEQ)
#define VOCAB 50000

typedef unsigned long long u64;

__device__ float g_xg[2u*NTOK*G4H];           // [dir][m=batch*SEQ+pos][1024]
__device__ float g_h [2u*NTOK*HDIM2];
__device__ float g_feats[NTOK*NTAGS];
__device__ float g_llh[BATCH];
__device__ int   g_cnt[16];
__device__ __nv_bfloat16 g_embbf[(size_t)VOCAB*EDIM];
__device__ __nv_bfloat16 g_wbf[2048u*EDIM];   // [dir*1024 + nl][256]

__device__ __forceinline__ void fma2(u64& acc, u64 a, u64 b) {
    asm("fma.rn.f32x2 %0, %1, %2, %0;" : "+l"(acc) : "l"(a), "l"(b));
}
__device__ __forceinline__ float foldlohi(u64 v) {
    float lo, hi; asm("mov.b64 {%0, %1}, %2;" : "=f"(lo), "=f"(hi) : "l"(v)); return lo + hi;
}
__device__ __forceinline__ float sigf(float x) { return __fdividef(1.f, 1.f + __expf(-x)); }
__device__ __forceinline__ float tanhfast(float x) {
    return 2.f * __fdividef(1.f, 1.f + __expf(-2.f * x)) - 1.f;
}
__device__ __forceinline__ uint32_t smem_u32(const void* p) {
    uint32_t a;
    asm("{ .reg .u64 t; cvta.to.shared.u64 t, %1; cvt.u32.u64 %0, t; }" : "=r"(a) : "l"(p));
    return a;
}
__device__ __forceinline__ void ldsm4(uint32_t* r, uint32_t addr) {
    asm volatile("ldmatrix.sync.aligned.m8n8.x4.shared.b16 {%0,%1,%2,%3}, [%4];"
                 : "=r"(r[0]), "=r"(r[1]), "=r"(r[2]), "=r"(r[3]) : "r"(addr));
}
__device__ __forceinline__ void mma16816(float* c, const uint32_t* a, const uint32_t* b) {
    asm volatile(
        "mma.sync.aligned.m16n8k16.row.col.f32.bf16.bf16.f32 "
        "{%0,%1,%2,%3}, {%4,%5,%6,%7}, {%8,%9}, {%0,%1,%2,%3};"
        : "+f"(c[0]), "+f"(c[1]), "+f"(c[2]), "+f"(c[3])
        : "r"(a[0]), "r"(a[1]), "r"(a[2]), "r"(a[3]), "r"(b[0]), "r"(b[1]));
}

// ============================================================================
// One-time conversions (memory-bound, ~15 us total)
// ============================================================================
__global__ void conv_emb_kernel(const float* __restrict__ emb) {
    const size_t i = (size_t)blockIdx.x * 256 + threadIdx.x;
    g_embbf[i] = __float2bfloat16(emb[i]);
}
__global__ void conv_w_kernel(const float* __restrict__ wihf, const float* __restrict__ wihb) {
    const int row = blockIdx.x;              // 0..2047 (dir-major)
    const int dir = row >> 10, nl = row & 1023;
    const float* src = (dir ? wihb : wihf) + (size_t)nl * EDIM;
    g_wbf[(size_t)row * EDIM + threadIdx.x] = __float2bfloat16(src[threadIdx.x]);
    if (row == 0 && threadIdx.x < 16) g_cnt[threadIdx.x] = 0;
}

// ============================================================================
// Kernel 1: input projection via bf16 HMMA (mma.sync m16n8k16, fp32 acc).
//   Tile 128x128, K=256 in 8 k-blocks of 32. 8 warps (2x4), warp = 64x32.
//   SMEM stride 40 bf16 (80 B): ldmatrix-phase conflict-free.
//   B = W rows [n][k] -> 'col' operand via non-transposed ldmatrix.
// ============================================================================
#define ALD 40

__global__ __launch_bounds__(256) void gemm_xg_hmma(
    const int* __restrict__ sent,
    const float* __restrict__ bihf, const float* __restrict__ bhhf,
    const float* __restrict__ bihb, const float* __restrict__ bhhb)
{
    __shared__ __nv_bfloat16 As[128 * ALD];
    __shared__ __nv_bfloat16 Bs[128 * ALD];
    __shared__ float biasS[128];

    const int tid   = threadIdx.x;
    const int ntile = blockIdx.x;     // 0..15
    const int mtile = blockIdx.y;     // 0..255
    const int dir   = ntile >> 3;
    const int nl0   = (ntile * 128) & 1023;

    if (tid < 128) {
        const float* bih = dir ? bihb : bihf;
        const float* bhh = dir ? bhhb : bhhf;
        biasS[tid] = bih[nl0 + tid] + bhh[nl0 + tid];
    }

    // staging: thread covers rows srow & srow+64, 16B chunk schunk (of 4)
    const int srow = tid >> 2, schunk = tid & 3;
    const int erow0 = sent[mtile * 128 + srow];
    const int erow1 = sent[mtile * 128 + srow + 64];
    const int wrow0 = dir * 1024 + ((ntile * 128 + srow) & 1023);
    const int wrow1 = dir * 1024 + ((ntile * 128 + srow + 64) & 1023);

    // prefetch k-block 0
    uint4 pa0 = *reinterpret_cast<const uint4*>(g_embbf + (size_t)erow0 * EDIM + schunk * 8);
    uint4 pa1 = *reinterpret_cast<const uint4*>(g_embbf + (size_t)erow1 * EDIM + schunk * 8);
    uint4 pb0 = *reinterpret_cast<const uint4*>(g_wbf + (size_t)wrow0 * EDIM + schunk * 8);
    uint4 pb1 = *reinterpret_cast<const uint4*>(g_wbf + (size_t)wrow1 * EDIM + schunk * 8);

    const int warp = tid >> 5, lane = tid & 31;
    const int mw = warp & 1, nw = warp >> 1;       // 2 x 4 warp grid
    const uint32_t asb = smem_u32(As), bsb = smem_u32(Bs);

    // ldmatrix lane addressing
    const int a_row  = lane & 15;
    const int a_koff = (lane >> 4) * 8;
    const int b_mi   = lane >> 3;
    const int b_row  = (lane & 7) + ((b_mi >> 1) << 3);
    const int b_koff = (b_mi & 1) * 8;

    float c[4][4][4];
#pragma unroll
    for (int mi = 0; mi < 4; mi++)
#pragma unroll
        for (int ni = 0; ni < 4; ni++)
#pragma unroll
            for (int q = 0; q < 4; q++) c[mi][ni][q] = 0.f;

    for (int kb = 0; kb < 8; kb++) {
        *reinterpret_cast<uint4*>(As + srow * ALD + schunk * 8)        = pa0;
        *reinterpret_cast<uint4*>(As + (srow + 64) * ALD + schunk * 8) = pa1;
        *reinterpret_cast<uint4*>(Bs + srow * ALD + schunk * 8)        = pb0;
        *reinterpret_cast<uint4*>(Bs + (srow + 64) * ALD + schunk * 8) = pb1;
        __syncthreads();

        if (kb < 7) {  // prefetch next k-block
            const int ko = (kb + 1) * 32 + schunk * 8;
            pa0 = *reinterpret_cast<const uint4*>(g_embbf + (size_t)erow0 * EDIM + ko);
            pa1 = *reinterpret_cast<const uint4*>(g_embbf + (size_t)erow1 * EDIM + ko);
            pb0 = *reinterpret_cast<const uint4*>(g_wbf + (size_t)wrow0 * EDIM + ko);
            pb1 = *reinterpret_cast<const uint4*>(g_wbf + (size_t)wrow1 * EDIM + ko);
        }

#pragma unroll
        for (int s = 0; s < 2; s++) {
            uint32_t a[4][4];
#pragma unroll
            for (int mi = 0; mi < 4; mi++) {
                const uint32_t addr = asb +
                    ((mw * 64 + mi * 16 + a_row) * ALD + s * 16 + a_koff) * 2;
                ldsm4(a[mi], addr);
            }
            uint32_t bb[4][2];
#pragma unroll
            for (int np = 0; np < 2; np++) {
                uint32_t r[4];
                const uint32_t addr = bsb +
                    ((nw * 32 + np * 16 + b_row) * ALD + s * 16 + b_koff) * 2;
                ldsm4(r, addr);
                bb[np * 2][0] = r[0]; bb[np * 2][1] = r[1];
                bb[np * 2 + 1][0] = r[2]; bb[np * 2 + 1][1] = r[3];
            }
#pragma unroll
            for (int mi = 0; mi < 4; mi++)
#pragma unroll
                for (int ni = 0; ni < 4; ni++)
                    mma16816(c[mi][ni], a[mi], bb[ni]);
        }
        __syncthreads();
    }

    // epilogue: thread t owns rows t/4 (+8), cols 2*(t%4) (+1) of each frag
    const int trow = lane >> 2, tcol = (lane & 3) * 2;
#pragma unroll
    for (int mi = 0; mi < 4; mi++) {
#pragma unroll
        for (int ni = 0; ni < 4; ni++) {
            const int m = mtile * 128 + mw * 64 + mi * 16 + trow;
            const int n = nw * 32 + ni * 8 + tcol;
            const float b0 = biasS[n], b1 = biasS[n + 1];
            float* base = g_xg + ((size_t)dir * NTOK + m) * G4H + nl0 + n;
            float2 v0; v0.x = c[mi][ni][0] + b0; v0.y = c[mi][ni][1] + b1;
            float2 v1; v1.x = c[mi][ni][2] + b0; v1.y = c[mi][ni][3] + b1;
            *reinterpret_cast<float2*>(base) = v0;
            *reinterpret_cast<float2*>(base + (size_t)8 * G4H) = v1;
        }
    }
}

// ============================================================================
// Kernel 2: persistent BiLSTM — R9 CHAMPION, verbatim.
// ============================================================================
#define HLD    260
#define PRE_LD 65

__global__ __launch_bounds__(256, 1) void lstm_kernel(
    const float* __restrict__ whhf, const float* __restrict__ whhb)
{
    __shared__ float hs[8 * HLD];
    __shared__ float pre[128 * PRE_LD];

    const int tid = threadIdx.x;
    const int blk = blockIdx.x;
    const int dir = blk >> 6;
    const int bg  = (blk >> 3) & 7;
    const int ug  = blk & 7;
    const float* __restrict__ whh = dir ? whhb : whhf;

    const int kc = tid & 7;
    const int r4 = tid >> 3;

    u64 w[4][16];
#pragma unroll
    for (int G = 0; G < 4; G++) {
        const float* wr = whh + (size_t)(G * 256 + ug * 32 + r4) * HDIM2;
#pragma unroll
        for (int q = 0; q < 8; q++) {
            ulonglong2 v = *reinterpret_cast<const ulonglong2*>(wr + q * 32 + kc * 4);
            w[G][2 * q] = v.x; w[G][2 * q + 1] = v.y;
        }
    }

    const int gb = tid >> 5;
    const int gu = tid & 31;
    const int b_glob = bg * 8 + gb;
    const int unit = ug * 32 + gu;
    const int cnt_idx = dir * 8 + bg;
    float c_state = 0.f;

    for (int t = 0; t < SEQ; t++) {
        const int pos = dir ? (SEQ - 1 - t) : t;

        const float* xp = g_xg + ((size_t)dir * NTOK + (size_t)b_glob * SEQ + pos) * G4H + unit;
        float x0 = __ldcs(xp);
        float x1 = __ldcs(xp + 256);
        float x2 = __ldcs(xp + 512);
        float x3 = __ldcs(xp + 768);

        if (t > 0) {
            if (tid == 0) {
                volatile int* c = &g_cnt[cnt_idx];
                const int target = 8 * t;
                while (*c < target) { }
            }
            __syncthreads();
            const int ppos = dir ? (pos + 1) : (pos - 1);
#pragma unroll
            for (int q = 0; q < 2; q++) {
                const int id = tid + q * 256;
                const int b = id >> 6, kf4 = id & 63;
                float4 v = __ldcg(reinterpret_cast<const float4*>(
                    g_h + ((size_t)(dir * BATCH + bg * 8 + b) * SEQ + ppos) * HDIM2 + kf4 * 4));
                *reinterpret_cast<float4*>(hs + b * HLD + kf4 * 4) = v;
            }
            __syncthreads();

#pragma unroll
            for (int p = 0; p < 2; p++) {
                u64 acc[4][4];
#pragma unroll
                for (int G = 0; G < 4; G++)
#pragma unroll
                    for (int b = 0; b < 4; b++) acc[G][b] = 0ull;
#pragma unroll
                for (int q = 0; q < 8; q++) {
#pragma unroll
                    for (int b = 0; b < 4; b++) {
                        const ulonglong2 hv = *reinterpret_cast<const ulonglong2*>(
                            hs + (p * 4 + b) * HLD + q * 32 + kc * 4);
#pragma unroll
                        for (int G = 0; G < 4; G++) {
                            fma2(acc[G][b], w[G][2 * q],     hv.x);
                            fma2(acc[G][b], w[G][2 * q + 1], hv.y);
                        }
                    }
                }
#pragma unroll
                for (int G = 0; G < 4; G++)
#pragma unroll
                    for (int b = 0; b < 4; b++)
                        pre[(G * 32 + r4) * PRE_LD + kc * 8 + p * 4 + b] = foldlohi(acc[G][b]);
            }
            __syncthreads();
        }

        {
            float pi = x0, pf = x1, pg = x2, po = x3;
            if (t > 0) {
#pragma unroll
                for (int k8 = 0; k8 < 8; k8++) {
                    pi += pre[(0 * 32 + gu) * PRE_LD + k8 * 8 + gb];
                    pf += pre[(1 * 32 + gu) * PRE_LD + k8 * 8 + gb];
                    pg += pre[(2 * 32 + gu) * PRE_LD + k8 * 8 + gb];
                    po += pre[(3 * 32 + gu) * PRE_LD + k8 * 8 + gb];
                }
            }
            c_state = sigf(pf) * c_state + sigf(pi) * tanhfast(pg);
            const float hv = sigf(po) * tanhfast(c_state);
            __stcg(&g_h[((size_t)(dir * BATCH + b_glob) * SEQ + pos) * HDIM2 + unit], hv);
        }

        __syncthreads();
        if (tid == 0) {
            __threadfence();
            atomicAdd(&g_cnt[cnt_idx], 1);
        }
    }
}

// ============================================================================
// Kernel 3: output projection
// ============================================================================
__global__ __launch_bounds__(256) void feats_kernel(
    const float* __restrict__ wout, const float* __restrict__ bout)
{
    __shared__ float wsm[NTAGS * 512];
    const int tid = threadIdx.x;
    for (int i = tid; i < NTAGS * 512; i += 256) wsm[i] = wout[i];
    __syncthreads();

    const int lane = tid & 31;
    const int warp = tid >> 5;

#pragma unroll
    for (int pass = 0; pass < 4; pass++) {
        const int m = blockIdx.x * 32 + pass * 8 + warp;
        const float* h0 = g_h + (size_t)m * HDIM2;
        const float* h1 = g_h + (size_t)NTOK * HDIM2 + (size_t)m * HDIM2;
        float acc[NTAGS];
#pragma unroll
        for (int tg = 0; tg < NTAGS; tg++) acc[tg] = 0.f;

#pragma unroll
        for (int kk = 0; kk < 16; kk++) {
            const int k = kk * 32 + lane;
            const float hv = (k < 256) ? h0[k] : h1[k - 256];
#pragma unroll
            for (int tg = 0; tg < NTAGS; tg++) acc[tg] += hv * wsm[tg * 512 + k];
        }
#pragma unroll
        for (int tg = 0; tg < NTAGS; tg++)
            for (int off = 16; off; off >>= 1)
                acc[tg] += __shfl_down_sync(0xffffffffu, acc[tg], off);
        if (lane == 0) {
#pragma unroll
            for (int tg = 0; tg < NTAGS; tg++)
                g_feats[(size_t)m * NTAGS + tg] = acc[tg] + bout[tg];
        }
    }
}

// ============================================================================
// Kernel 4: CRF per-sequence llh (mask all-ones)
// ============================================================================
__global__ __launch_bounds__(32) void crf_kernel(
    const int* __restrict__ tags,
    const float* __restrict__ startt, const float* __restrict__ endt,
    const float* __restrict__ trans)
{
    const int b = blockIdx.x;
    const int lane = threadIdx.x;
    const float* __restrict__ em = g_feats + (size_t)b * SEQ * NTAGS;
    const int* __restrict__ tg = tags + (size_t)b * SEQ;

    float sc = 0.f;
    for (int s = lane; s < SEQ; s += 32) {
        const int tc = tg[s];
        sc += em[s * NTAGS + tc];
        if (s > 0) sc += trans[tg[s - 1] * NTAGS + tc];
    }
    for (int off = 16; off; off >>= 1) sc += __shfl_down_sync(0xffffffffu, sc, off);

    const int j = lane < NTAGS ? lane : NTAGS - 1;
    float tcol[NTAGS];
#pragma unroll
    for (int i = 0; i < NTAGS; i++) tcol[i] = trans[i * NTAGS + j];

    float alpha = startt[j] + em[j];
    for (int s = 1; s < SEQ; s++) {
        float v[NTAGS];
        float mx = -1e30f;
#pragma unroll
        for (int i = 0; i < NTAGS; i++) {
            const float ai = __shfl_sync(0xffffffffu, alpha, i);
            v[i] = ai + tcol[i];
            mx = fmaxf(mx, v[i]);
        }
        float sum = 0.f;
#pragma unroll
        for (int i = 0; i < NTAGS; i++) sum += __expf(v[i] - mx);
        alpha = mx + __logf(sum) + em[s * NTAGS + j];
    }

    float z = (lane < NTAGS) ? (alpha + endt[j]) : -1e30f;
    float mz = z;
    for (int off = 16; off; off >>= 1) mz = fmaxf(mz, __shfl_down_sync(0xffffffffu, mz, off));
    mz = __shfl_sync(0xffffffffu, mz, 0);
    float ez = __expf(z - mz);
    for (int off = 16; off; off >>= 1) ez += __shfl_down_sync(0xffffffffu, ez, off);

    if (lane == 0) {
        const float logZ = mz + __logf(ez);
        const float score = sc + startt[tg[0]] + endt[tg[SEQ - 1]];
        g_llh[b] = score - logZ;
    }
}

__global__ void final_kernel(float* out) {
    __shared__ float red[64];
    const int t = threadIdx.x;
    red[t] = g_llh[t];
    __syncthreads();
    for (int off = 32; off; off >>= 1) {
        if (t < off) red[t] += red[t + off];
        __syncthreads();
    }
    if (t == 0) out[0] = -red[0] / (float)BATCH;
}

// ============================================================================
extern "C" void kernel_launch(void* const* d_in, const int* in_sizes, int n_in,
                              void* d_out, int out_size)
{
    const int*   sent  = (const int*)  d_in[0];
    const int*   tags  = (const int*)  d_in[1];
    const float* emb   = (const float*)d_in[3];
    const float* wihf  = (const float*)d_in[4];
    const float* whhf  = (const float*)d_in[5];
    const float* bihf  = (const float*)d_in[6];
    const float* bhhf  = (const float*)d_in[7];
    const float* wihb  = (const float*)d_in[8];
    const float* whhb  = (const float*)d_in[9];
    const float* bihb  = (const float*)d_in[10];
    const float* bhhb  = (const float*)d_in[11];
    const float* wout  = (const float*)d_in[12];
    const float* bout  = (const float*)d_in[13];
    const float* startt= (const float*)d_in[14];
    const float* endt  = (const float*)d_in[15];
    const float* trans = (const float*)d_in[16];

    conv_emb_kernel<<<VOCAB, 256>>>(emb);
    conv_w_kernel<<<2048, 256>>>(wihf, wihb);
    gemm_xg_hmma<<<dim3(16, 256), 256>>>(sent, bihf, bhhf, bihb, bhhb);
    lstm_kernel<<<128, 256>>>(whhf, whhb);
    feats_kernel<<<1024, 256>>>(wout, bout);
    crf_kernel<<<64, 32>>>(tags, startt, endt, trans);
    final_kernel<<<1, 64>>>((float*)d_out);
}

// round 17
// speedup vs baseline: 2.8070x; 1.3744x over previous
#include <cuda_runtime.h>
#include <cuda_bf16.h>
#include <math.h>
#include <cstdint>

#define BATCH 64
#define SEQ   512
#define EDIM  256
#define HDIM2 256
#define G4H   1024
#define NTAGS 9
#define NTOK  (BATCH*SEQ)
#define VOCAB 50000

typedef unsigned long long u64;

__device__ float g_xg[2u*NTOK*G4H];           // [dir][m=batch*SEQ+pos][1024]
__device__ float g_h [2u*NTOK*HDIM2];
__device__ float g_feats[NTOK*NTAGS];
__device__ float g_llh[BATCH];
__device__ int   g_cnt[16];
__device__ __nv_bfloat16 g_embbf[(size_t)VOCAB*EDIM];
__device__ __nv_bfloat16 g_wbf[2048u*EDIM];   // [dir*1024 + nl][256]

__device__ __forceinline__ float sigf(float x) { return __fdividef(1.f, 1.f + __expf(-x)); }
__device__ __forceinline__ float tanhfast(float x) {
    return 2.f * __fdividef(1.f, 1.f + __expf(-2.f * x)) - 1.f;
}
__device__ __forceinline__ uint32_t smem_u32(const void* p) {
    uint32_t a;
    asm("{ .reg .u64 t; cvta.to.shared.u64 t, %1; cvt.u32.u64 %0, t; }" : "=r"(a) : "l"(p));
    return a;
}
__device__ __forceinline__ void ldsm4(uint32_t* r, uint32_t addr) {
    asm volatile("ldmatrix.sync.aligned.m8n8.x4.shared.b16 {%0,%1,%2,%3}, [%4];"
                 : "=r"(r[0]), "=r"(r[1]), "=r"(r[2]), "=r"(r[3]) : "r"(addr));
}
__device__ __forceinline__ void mma16816(float* c, const uint32_t* a, const uint32_t* b) {
    asm volatile(
        "mma.sync.aligned.m16n8k16.row.col.f32.bf16.bf16.f32 "
        "{%0,%1,%2,%3}, {%4,%5,%6,%7}, {%8,%9}, {%0,%1,%2,%3};"
        : "+f"(c[0]), "+f"(c[1]), "+f"(c[2]), "+f"(c[3])
        : "r"(a[0]), "r"(a[1]), "r"(a[2]), "r"(a[3]), "r"(b[0]), "r"(b[1]));
}
__device__ __forceinline__ void mma1688_tf32(float* c, const uint32_t* a, uint32_t b0, uint32_t b1) {
    asm volatile(
        "mma.sync.aligned.m16n8k8.row.col.f32.tf32.tf32.f32 "
        "{%0,%1,%2,%3}, {%4,%5,%6,%7}, {%8,%9}, {%0,%1,%2,%3};"
        : "+f"(c[0]), "+f"(c[1]), "+f"(c[2]), "+f"(c[3])
        : "r"(a[0]), "r"(a[1]), "r"(a[2]), "r"(a[3]), "r"(b0), "r"(b1));
}
__device__ __forceinline__ uint32_t cvt_tf32(float x) {
    uint32_t r; asm("cvt.rna.tf32.f32 %0, %1;" : "=r"(r) : "f"(x)); return r;
}

// ============================================================================
// One-time conversions
// ============================================================================
__global__ void conv_emb_kernel(const float* __restrict__ emb) {
    const size_t i = (size_t)blockIdx.x * 256 + threadIdx.x;
    g_embbf[i] = __float2bfloat16(emb[i]);
}
__global__ void conv_w_kernel(const float* __restrict__ wihf, const float* __restrict__ wihb) {
    const int row = blockIdx.x;
    const int dir = row >> 10, nl = row & 1023;
    const float* src = (dir ? wihb : wihf) + (size_t)nl * EDIM;
    g_wbf[(size_t)row * EDIM + threadIdx.x] = __float2bfloat16(src[threadIdx.x]);
    if (row == 0 && threadIdx.x < 16) g_cnt[threadIdx.x] = 0;
}

// ============================================================================
// Kernel 1: input projection via bf16 HMMA — R16 champion, verbatim.
// ============================================================================
#define ALD 40

__global__ __launch_bounds__(256) void gemm_xg_hmma(
    const int* __restrict__ sent,
    const float* __restrict__ bihf, const float* __restrict__ bhhf,
    const float* __restrict__ bihb, const float* __restrict__ bhhb)
{
    __shared__ __nv_bfloat16 As[128 * ALD];
    __shared__ __nv_bfloat16 Bs[128 * ALD];
    __shared__ float biasS[128];

    const int tid   = threadIdx.x;
    const int ntile = blockIdx.x;
    const int mtile = blockIdx.y;
    const int dir   = ntile >> 3;
    const int nl0   = (ntile * 128) & 1023;

    if (tid < 128) {
        const float* bih = dir ? bihb : bihf;
        const float* bhh = dir ? bhhb : bhhf;
        biasS[tid] = bih[nl0 + tid] + bhh[nl0 + tid];
    }

    const int srow = tid >> 2, schunk = tid & 3;
    const int erow0 = sent[mtile * 128 + srow];
    const int erow1 = sent[mtile * 128 + srow + 64];
    const int wrow0 = dir * 1024 + ((ntile * 128 + srow) & 1023);
    const int wrow1 = dir * 1024 + ((ntile * 128 + srow + 64) & 1023);

    uint4 pa0 = *reinterpret_cast<const uint4*>(g_embbf + (size_t)erow0 * EDIM + schunk * 8);
    uint4 pa1 = *reinterpret_cast<const uint4*>(g_embbf + (size_t)erow1 * EDIM + schunk * 8);
    uint4 pb0 = *reinterpret_cast<const uint4*>(g_wbf + (size_t)wrow0 * EDIM + schunk * 8);
    uint4 pb1 = *reinterpret_cast<const uint4*>(g_wbf + (size_t)wrow1 * EDIM + schunk * 8);

    const int warp = tid >> 5, lane = tid & 31;
    const int mw = warp & 1, nw = warp >> 1;
    const uint32_t asb = smem_u32(As), bsb = smem_u32(Bs);

    const int a_row  = lane & 15;
    const int a_koff = (lane >> 4) * 8;
    const int b_mi   = lane >> 3;
    const int b_row  = (lane & 7) + ((b_mi >> 1) << 3);
    const int b_koff = (b_mi & 1) * 8;

    float c[4][4][4];
#pragma unroll
    for (int mi = 0; mi < 4; mi++)
#pragma unroll
        for (int ni = 0; ni < 4; ni++)
#pragma unroll
            for (int q = 0; q < 4; q++) c[mi][ni][q] = 0.f;

    for (int kb = 0; kb < 8; kb++) {
        *reinterpret_cast<uint4*>(As + srow * ALD + schunk * 8)        = pa0;
        *reinterpret_cast<uint4*>(As + (srow + 64) * ALD + schunk * 8) = pa1;
        *reinterpret_cast<uint4*>(Bs + srow * ALD + schunk * 8)        = pb0;
        *reinterpret_cast<uint4*>(Bs + (srow + 64) * ALD + schunk * 8) = pb1;
        __syncthreads();

        if (kb < 7) {
            const int ko = (kb + 1) * 32 + schunk * 8;
            pa0 = *reinterpret_cast<const uint4*>(g_embbf + (size_t)erow0 * EDIM + ko);
            pa1 = *reinterpret_cast<const uint4*>(g_embbf + (size_t)erow1 * EDIM + ko);
            pb0 = *reinterpret_cast<const uint4*>(g_wbf + (size_t)wrow0 * EDIM + ko);
            pb1 = *reinterpret_cast<const uint4*>(g_wbf + (size_t)wrow1 * EDIM + ko);
        }

#pragma unroll
        for (int s = 0; s < 2; s++) {
            uint32_t a[4][4];
#pragma unroll
            for (int mi = 0; mi < 4; mi++) {
                const uint32_t addr = asb +
                    ((mw * 64 + mi * 16 + a_row) * ALD + s * 16 + a_koff) * 2;
                ldsm4(a[mi], addr);
            }
            uint32_t bb[4][2];
#pragma unroll
            for (int np = 0; np < 2; np++) {
                uint32_t r[4];
                const uint32_t addr = bsb +
                    ((nw * 32 + np * 16 + b_row) * ALD + s * 16 + b_koff) * 2;
                ldsm4(r, addr);
                bb[np * 2][0] = r[0]; bb[np * 2][1] = r[1];
                bb[np * 2 + 1][0] = r[2]; bb[np * 2 + 1][1] = r[3];
            }
#pragma unroll
            for (int mi = 0; mi < 4; mi++)
#pragma unroll
                for (int ni = 0; ni < 4; ni++)
                    mma16816(c[mi][ni], a[mi], bb[ni]);
        }
        __syncthreads();
    }

    const int trow = lane >> 2, tcol = (lane & 3) * 2;
#pragma unroll
    for (int mi = 0; mi < 4; mi++) {
#pragma unroll
        for (int ni = 0; ni < 4; ni++) {
            const int m = mtile * 128 + mw * 64 + mi * 16 + trow;
            const int n = nw * 32 + ni * 8 + tcol;
            const float b0 = biasS[n], b1 = biasS[n + 1];
            float* base = g_xg + ((size_t)dir * NTOK + m) * G4H + nl0 + n;
            float2 v0; v0.x = c[mi][ni][0] + b0; v0.y = c[mi][ni][1] + b1;
            float2 v1; v1.x = c[mi][ni][2] + b0; v1.y = c[mi][ni][3] + b1;
            *reinterpret_cast<float2*>(base) = v0;
            *reinterpret_cast<float2*>(base + (size_t)8 * G4H) = v1;
        }
    }
}

// ============================================================================
// Kernel 2: persistent BiLSTM — R9 protocol + TF32 mma.sync matvec.
//   128 CTAs = dir(2) x bg(8) x ug(8), 8 warps. Warp w owns gate w>>1,
//   units ug*32 + (w&1)*16 .. +16 (M-tile of 16 rows), all 256 k, 8 batches.
//   Weights as TF32 A-fragments in regs (128 u32). h staged tf32-rounded;
//   B-frag via 2 scalar LDS (bank-clean). pre[] holds fully-reduced dots.
// ============================================================================
#define HLD    260
#define PRE_LD 9

__global__ __launch_bounds__(256, 1) void lstm_kernel(
    const float* __restrict__ whhf, const float* __restrict__ whhb)
{
    __shared__ float hs[8 * HLD];        // staged h_prev [batch][256] (tf32-rounded)
    __shared__ float pre[128 * PRE_LD];  // [local row][batch]

    const int tid = threadIdx.x;
    const int blk = blockIdx.x;
    const int dir = blk >> 6;
    const int bg  = (blk >> 3) & 7;
    const int ug  = blk & 7;
    const float* __restrict__ whh = dir ? whhb : whhf;

    const int lane = tid & 31, warp = tid >> 5;
    const int G  = warp >> 1;                       // gate 0..3
    const int ur = ug * 32 + (warp & 1) * 16;       // unit base of this M-tile

    // TF32 A-fragments: wf[j][0..3] for k-step j (k = j*8 + ...)
    uint32_t wf[32][4];
    {
        const int row0 = G * 256 + ur + (lane >> 2);
        const float* w0 = whh + (size_t)row0 * HDIM2;
        const float* w8 = whh + (size_t)(row0 + 8) * HDIM2;
        const int kl = lane & 3;
#pragma unroll
        for (int j = 0; j < 32; j++) {
            wf[j][0] = cvt_tf32(w0[j * 8 + kl]);
            wf[j][1] = cvt_tf32(w8[j * 8 + kl]);
            wf[j][2] = cvt_tf32(w0[j * 8 + kl + 4]);
            wf[j][3] = cvt_tf32(w8[j * 8 + kl + 4]);
        }
    }

    const int gb = tid >> 5;          // gate phase: batch 0..7
    const int gu = tid & 31;          // unit-in-slice 0..31
    const int b_glob = bg * 8 + gb;
    const int unit = ug * 32 + gu;
    const int cnt_idx = dir * 8 + bg;
    float c_state = 0.f;

    // mma lane addressing for B / C
    const int mb = lane >> 2;         // B batch / C row-in-8
    const int mk = lane & 3;          // B k / C col pair
    const int prow = (warp >> 1) * 32 + (warp & 1) * 16 + mb;  // local row of c0/c1

    for (int t = 0; t < SEQ; t++) {
        const int pos = dir ? (SEQ - 1 - t) : t;

        // prefetch x-preacts before the inter-CTA wait
        const float* xp = g_xg + ((size_t)dir * NTOK + (size_t)b_glob * SEQ + pos) * G4H + unit;
        float x0 = __ldcs(xp);
        float x1 = __ldcs(xp + 256);
        float x2 = __ldcs(xp + 512);
        float x3 = __ldcs(xp + 768);

        if (t > 0) {
            if (tid == 0) {
                volatile int* c = &g_cnt[cnt_idx];
                const int target = 8 * t;
                while (*c < target) { }
            }
            __syncthreads();
            const int ppos = dir ? (pos + 1) : (pos - 1);
            // stage h_prev (tf32-rounded) for our 8 batches
#pragma unroll
            for (int q = 0; q < 2; q++) {
                const int id = tid + q * 256;
                const int b = id >> 6, kf4 = id & 63;
                float4 v = __ldcg(reinterpret_cast<const float4*>(
                    g_h + ((size_t)(dir * BATCH + bg * 8 + b) * SEQ + ppos) * HDIM2 + kf4 * 4));
                float4 o;
                o.x = __uint_as_float(cvt_tf32(v.x));
                o.y = __uint_as_float(cvt_tf32(v.y));
                o.z = __uint_as_float(cvt_tf32(v.z));
                o.w = __uint_as_float(cvt_tf32(v.w));
                *reinterpret_cast<float4*>(hs + b * HLD + kf4 * 4) = o;
            }
            __syncthreads();

            // matvec via 32 x mma.m16n8k8.tf32 : D[16 rows][8 batches] per warp
            float c[4] = {0.f, 0.f, 0.f, 0.f};
            const float* hb = hs + mb * HLD + mk;
#pragma unroll
            for (int j = 0; j < 32; j++) {
                const uint32_t b0 = __float_as_uint(hb[j * 8]);
                const uint32_t b1 = __float_as_uint(hb[j * 8 + 4]);
                mma1688_tf32(c, wf[j], b0, b1);
            }
            pre[prow * PRE_LD + 2 * mk]           = c[0];
            pre[prow * PRE_LD + 2 * mk + 1]       = c[1];
            pre[(prow + 8) * PRE_LD + 2 * mk]     = c[2];
            pre[(prow + 8) * PRE_LD + 2 * mk + 1] = c[3];
            __syncthreads();
        }

        // gate phase: thread owns (batch gb, unit gu); partials fully reduced
        {
            float pi = x0, pf = x1, pg = x2, po = x3;
            if (t > 0) {
                pi += pre[(0 * 32 + gu) * PRE_LD + gb];
                pf += pre[(1 * 32 + gu) * PRE_LD + gb];
                pg += pre[(2 * 32 + gu) * PRE_LD + gb];
                po += pre[(3 * 32 + gu) * PRE_LD + gb];
            }
            c_state = sigf(pf) * c_state + sigf(pi) * tanhfast(pg);
            const float hv = sigf(po) * tanhfast(c_state);
            __stcg(&g_h[((size_t)(dir * BATCH + b_glob) * SEQ + pos) * HDIM2 + unit], hv);
        }

        __syncthreads();
        if (tid == 0) {
            __threadfence();
            atomicAdd(&g_cnt[cnt_idx], 1);
        }
    }
}

// ============================================================================
// Kernel 3: output projection
// ============================================================================
__global__ __launch_bounds__(256) void feats_kernel(
    const float* __restrict__ wout, const float* __restrict__ bout)
{
    __shared__ float wsm[NTAGS * 512];
    const int tid = threadIdx.x;
    for (int i = tid; i < NTAGS * 512; i += 256) wsm[i] = wout[i];
    __syncthreads();

    const int lane = tid & 31;
    const int warp = tid >> 5;

#pragma unroll
    for (int pass = 0; pass < 4; pass++) {
        const int m = blockIdx.x * 32 + pass * 8 + warp;
        const float* h0 = g_h + (size_t)m * HDIM2;
        const float* h1 = g_h + (size_t)NTOK * HDIM2 + (size_t)m * HDIM2;
        float acc[NTAGS];
#pragma unroll
        for (int tg = 0; tg < NTAGS; tg++) acc[tg] = 0.f;

#pragma unroll
        for (int kk = 0; kk < 16; kk++) {
            const int k = kk * 32 + lane;
            const float hv = (k < 256) ? h0[k] : h1[k - 256];
#pragma unroll
            for (int tg = 0; tg < NTAGS; tg++) acc[tg] += hv * wsm[tg * 512 + k];
        }
#pragma unroll
        for (int tg = 0; tg < NTAGS; tg++)
            for (int off = 16; off; off >>= 1)
                acc[tg] += __shfl_down_sync(0xffffffffu, acc[tg], off);
        if (lane == 0) {
#pragma unroll
            for (int tg = 0; tg < NTAGS; tg++)
                g_feats[(size_t)m * NTAGS + tg] = acc[tg] + bout[tg];
        }
    }
}

// ============================================================================
// Kernel 4: CRF per-sequence llh (mask all-ones)
// ============================================================================
__global__ __launch_bounds__(32) void crf_kernel(
    const int* __restrict__ tags,
    const float* __restrict__ startt, const float* __restrict__ endt,
    const float* __restrict__ trans)
{
    const int b = blockIdx.x;
    const int lane = threadIdx.x;
    const float* __restrict__ em = g_feats + (size_t)b * SEQ * NTAGS;
    const int* __restrict__ tg = tags + (size_t)b * SEQ;

    float sc = 0.f;
    for (int s = lane; s < SEQ; s += 32) {
        const int tc = tg[s];
        sc += em[s * NTAGS + tc];
        if (s > 0) sc += trans[tg[s - 1] * NTAGS + tc];
    }
    for (int off = 16; off; off >>= 1) sc += __shfl_down_sync(0xffffffffu, sc, off);

    const int j = lane < NTAGS ? lane : NTAGS - 1;
    float tcol[NTAGS];
#pragma unroll
    for (int i = 0; i < NTAGS; i++) tcol[i] = trans[i * NTAGS + j];

    float alpha = startt[j] + em[j];
    for (int s = 1; s < SEQ; s++) {
        float v[NTAGS];
        float mx = -1e30f;
#pragma unroll
        for (int i = 0; i < NTAGS; i++) {
            const float ai = __shfl_sync(0xffffffffu, alpha, i);
            v[i] = ai + tcol[i];
            mx = fmaxf(mx, v[i]);
        }
        float sum = 0.f;
#pragma unroll
        for (int i = 0; i < NTAGS; i++) sum += __expf(v[i] - mx);
        alpha = mx + __logf(sum) + em[s * NTAGS + j];
    }

    float z = (lane < NTAGS) ? (alpha + endt[j]) : -1e30f;
    float mz = z;
    for (int off = 16; off; off >>= 1) mz = fmaxf(mz, __shfl_down_sync(0xffffffffu, mz, off));
    mz = __shfl_sync(0xffffffffu, mz, 0);
    float ez = __expf(z - mz);
    for (int off = 16; off; off >>= 1) ez += __shfl_down_sync(0xffffffffu, ez, off);

    if (lane == 0) {
        const float logZ = mz + __logf(ez);
        const float score = sc + startt[tg[0]] + endt[tg[SEQ - 1]];
        g_llh[b] = score - logZ;
    }
}

__global__ void final_kernel(float* out) {
    __shared__ float red[64];
    const int t = threadIdx.x;
    red[t] = g_llh[t];
    __syncthreads();
    for (int off = 32; off; off >>= 1) {
        if (t < off) red[t] += red[t + off];
        __syncthreads();
    }
    if (t == 0) out[0] = -red[0] / (float)BATCH;
}

// ============================================================================
extern "C" void kernel_launch(void* const* d_in, const int* in_sizes, int n_in,
                              void* d_out, int out_size)
{
    const int*   sent  = (const int*)  d_in[0];
    const int*   tags  = (const int*)  d_in[1];
    const float* emb   = (const float*)d_in[3];
    const float* wihf  = (const float*)d_in[4];
    const float* whhf  = (const float*)d_in[5];
    const float* bihf  = (const float*)d_in[6];
    const float* bhhf  = (const float*)d_in[7];
    const float* wihb  = (const float*)d_in[8];
    const float* whhb  = (const float*)d_in[9];
    const float* bihb  = (const float*)d_in[10];
    const float* bhhb  = (const float*)d_in[11];
    const float* wout  = (const float*)d_in[12];
    const float* bout  = (const float*)d_in[13];
    const float* startt= (const float*)d_in[14];
    const float* endt  = (const float*)d_in[15];
    const float* trans = (const float*)d_in[16];

    conv_emb_kernel<<<VOCAB, 256>>>(emb);
    conv_w_kernel<<<2048, 256>>>(wihf, wihb);
    gemm_xg_hmma<<<dim3(16, 256), 256>>>(sent, bihf, bhhf, bihb, bhhb);
    lstm_kernel<<<128, 256>>>(whhf, whhb);
    feats_kernel<<<1024, 256>>>(wout, bout);
    crf_kernel<<<64, 32>>>(tags, startt, endt, trans);
    final_kernel<<<1, 64>>>((float*)d_out);
}